// round 8
// baseline (speedup 1.0000x reference)
#include <cuda_runtime.h>
#include <cuda_fp16.h>
#include <math.h>

#define NN      50000
#define NE      800000
#define HID     128
#define NG      1024
#define NATOMS  100
#define NLAYERS 3
#define WPAD    132          // stride 132 words: conflict-free LDS128 on Wt

// ---------------- scratch (device globals; no allocation allowed) -------------
__device__ float  g_buf0[NN * HID];   // sel 0
__device__ float  g_buf1[NN * HID];   // sel 1
__device__ float  g_buf2[NN * HID];   // sel 2
__device__ __half g_h16[NN * HID];    // fp16 h for edge gathers
__device__ float  g_wt[5 * HID * HID];// pre-transposed weights Wt[c][k]
__device__ int   g_deg[NN + 1];
__device__ int   g_rowptr[NN + 1];
__device__ int   g_cursor[NN];
__device__ int   g_cval[64];
__device__ int   g_cflag[64];
__device__ int   g_esrc[NE];
__device__ float g_ea2[NE];

__device__ __forceinline__ float* bufsel(int s) {
    return s == 0 ? g_buf0 : (s == 1 ? g_buf1 : g_buf2);
}

// packed f32x2 FMA: d = a*b + d elementwise on two fp32 lanes
__device__ __forceinline__ void ffma2(unsigned long long& d,
                                      unsigned long long a,
                                      unsigned long long b) {
    asm("fma.rn.f32x2 %0, %1, %2, %0;" : "+l"(d) : "l"(a), "l"(b));
}
__device__ __forceinline__ float2 unpack2(unsigned long long u) {
    float2 v;
    asm("mov.b64 {%0, %1}, %2;" : "=f"(v.x), "=f"(v.y) : "l"(u));
    return v;
}

// ---------------- weight pre-transpose (runs once per launch, ~2us) -----------
// W[k][c] (row-major 128x128) -> g_wt[m][c][k]
__global__ void transpose_w_kernel(const float* __restrict__ wa,
                                   const float* __restrict__ lin) {
    __shared__ float t[32][33];
    int m = blockIdx.z;
    const float* src = (m < 3) ? wa + (size_t)m * HID * HID
                               : lin + (size_t)(m - 3) * HID * HID;
    float* dst = g_wt + (size_t)m * HID * HID;
    int x = blockIdx.x * 32 + threadIdx.x;
    int y0 = blockIdx.y * 32;
    #pragma unroll
    for (int dy = threadIdx.y; dy < 32; dy += 8)
        t[dy][threadIdx.x] = src[(size_t)(y0 + dy) * HID + x];
    __syncthreads();
    int xo = blockIdx.y * 32 + threadIdx.x;
    int yo0 = blockIdx.x * 32;
    #pragma unroll
    for (int dy = threadIdx.y; dy < 32; dy += 8)
        dst[(size_t)(yo0 + dy) * HID + xo] = t[threadIdx.x][dy];
}

// ---------------- embedding gather + all zero-init ----------------------------
__global__ void embed_kernel(const int* __restrict__ x_ori,
                             const float* __restrict__ embd,
                             const float* __restrict__ wp_b,
                             float* __restrict__ out) {
    int i = blockIdx.x * blockDim.x + threadIdx.x;   // over NN*32 float4
    if (i <= NN) g_deg[i] = 0;
    if (i < NN)  g_cursor[i] = 0;
    if (i < NG)  out[i] = wp_b[0];
    if (i < 64)  { g_cflag[i] = 0; g_cval[i] = 0; }
    if (i >= NN * (HID / 4)) return;
    int n = i >> 5;
    int c = i & 31;
    ((float4*)g_buf0)[i] = ((const float4*)(embd + x_ori[n] * HID))[c];
}

// ---------------- edge preprocessing ----------------------------------------
__global__ void count_deg_kernel(const int* __restrict__ dst) {
    int e = blockIdx.x * blockDim.x + threadIdx.x;
    if (e < NE) atomicAdd(&g_deg[dst[e]], 1);
}

// fused exclusive scan over g_deg -> g_rowptr, chained-lookback (49 blocks)
__global__ void scan_fused_kernel() {
    __shared__ int wsum[32];
    __shared__ int s_pref;
    int tid = threadIdx.x, bid = blockIdx.x;
    int i = bid * 1024 + tid;
    int v = (i < NN) ? g_deg[i] : 0;
    int x = v;
    #pragma unroll
    for (int o = 1; o < 32; o <<= 1) {
        int y = __shfl_up_sync(0xffffffffu, x, o);
        if ((tid & 31) >= o) x += y;
    }
    if ((tid & 31) == 31) wsum[tid >> 5] = x;
    __syncthreads();
    if (tid < 32) {
        int w = wsum[tid];
        #pragma unroll
        for (int o = 1; o < 32; o <<= 1) {
            int y = __shfl_up_sync(0xffffffffu, w, o);
            if (tid >= o) w += y;
        }
        wsum[tid] = w;
    }
    __syncthreads();
    int incl = x + ((tid >= 32) ? wsum[(tid >> 5) - 1] : 0);
    if (tid == 1023) {
        int pref = 0;
        if (bid > 0) {
            while (atomicAdd(&g_cflag[bid - 1], 0) == 0) { }
            pref = g_cval[bid - 1];
        }
        g_cval[bid] = pref + incl;
        __threadfence();
        atomicExch(&g_cflag[bid], 1);
        s_pref = pref;
    }
    __syncthreads();
    if (i < NN) g_rowptr[i] = s_pref + incl - v;   // exclusive
    if (i == NN - 1) g_rowptr[NN] = NE;
}

__global__ void scatter_edges_kernel(const int* __restrict__ src,
                                     const int* __restrict__ dst,
                                     const float* __restrict__ ea) {
    int e = blockIdx.x * blockDim.x + threadIdx.x;
    if (e >= NE) return;
    int d = dst[e];
    int p = g_rowptr[d] + atomicAdd(&g_cursor[d], 1);
    g_esrc[p] = src[e];
    float a = ea[e];
    g_ea2[p] = a * a;
}

// ---------------- GEMM + ReLU via packed f32x2 --------------------------------
// block = 512 threads, tile = 128 rows x 128 cols, K=128 in smem, 1 CTA/SM.
// Wt (pre-transposed in global) staged coalesced + conflict-free.
// Warp handles 8 rows: A-operand smem loads are warp-broadcast (N=1 phases).
// out_sel 0/1/2 -> fp32 buffers; out_sel 3 -> fp16 g_h16.
__global__ void __launch_bounds__(512, 1)
gemm_relu_kernel(int in_sel, int out_sel, int wsel,
                 const float* __restrict__ b) {
    extern __shared__ float sm[];
    float* Wt = sm;                  // [128 c][WPAD k]
    float* As = sm + HID * WPAD;     // [128 r][128 k]
    const float* X = bufsel(in_sel);
    const float* WtG = g_wt + (size_t)wsel * HID * HID;
    int tid  = threadIdx.x;
    int lane = tid & 31;
    int wid  = tid >> 5;             // 0..15
    int row0 = blockIdx.x * 128;

    // stage Wt: consecutive lanes -> consecutive k words (conflict-free, coalesced)
    #pragma unroll
    for (int i = tid; i < HID * HID; i += 512) {
        int c = i >> 7, k = i & 127;
        Wt[c * WPAD + k] = WtG[i];
    }
    // stage A rows (float4, conflict-free)
    #pragma unroll
    for (int i = tid; i < 128 * (HID / 4); i += 512) {
        int r = i >> 5, c = i & 31;
        int row = row0 + r;
        ((float4*)As)[i] = (row < NN) ? ((const float4*)(X + (size_t)row * HID))[c]
                                      : make_float4(0.f, 0.f, 0.f, 0.f);
    }
    __syncthreads();

    unsigned long long acc[8][4];    // [row][colgrp], f32x2 = even/odd-k partials
    #pragma unroll
    for (int r = 0; r < 8; r++)
        #pragma unroll
        for (int j = 0; j < 4; j++) acc[r][j] = 0ull;

    const int rbase = wid * 8;
    #pragma unroll 4
    for (int k4 = 0; k4 < 32; k4++) {
        ulonglong2 wv[4];
        #pragma unroll
        for (int j = 0; j < 4; j++)
            wv[j] = *(const ulonglong2*)&Wt[(lane + 32 * j) * WPAD + 4 * k4];
        #pragma unroll
        for (int r = 0; r < 8; r++) {
            ulonglong2 av = ((const ulonglong2*)As)[(rbase + r) * 32 + k4];
            #pragma unroll
            for (int j = 0; j < 4; j++) {
                ffma2(acc[r][j], av.x, wv[j].x);
                ffma2(acc[r][j], av.y, wv[j].y);
            }
        }
    }

    float bb[4];
    #pragma unroll
    for (int j = 0; j < 4; j++) bb[j] = b[lane + 32 * j];

    if (out_sel == 3) {
        #pragma unroll
        for (int r = 0; r < 8; r++) {
            int row = row0 + rbase + r;
            if (row < NN) {
                #pragma unroll
                for (int j = 0; j < 4; j++) {
                    float2 p = unpack2(acc[r][j]);
                    float v = fmaxf(p.x + p.y + bb[j], 0.f);
                    g_h16[(size_t)row * HID + lane + 32 * j] = __float2half(v);
                }
            }
        }
    } else {
        float* O = bufsel(out_sel);
        #pragma unroll
        for (int r = 0; r < 8; r++) {
            int row = row0 + rbase + r;
            if (row < NN) {
                #pragma unroll
                for (int j = 0; j < 4; j++) {
                    float2 p = unpack2(acc[r][j]);
                    O[(size_t)row * HID + lane + 32 * j] =
                        fmaxf(p.x + p.y + bb[j], 0.f);
                }
            }
        }
    }
}

// ---------------- aggregation + residual + normalize -------------------------
// one WARP per node; lane holds 4 adjacent cols (fp16 gather = 8B/lane);
// inner loop batched by 8 for MLP=8
__global__ void agg_norm_kernel(int x_sel, int o_sel,
                                const float* __restrict__ gamma_l,
                                const int* __restrict__ x_ori) {
    int n = (blockIdx.x * blockDim.x + threadIdx.x) >> 5;
    int lane = threadIdx.x & 31;
    const float4* X4 = (const float4*)bufsel(x_sel);
    float4*       O4 = (float4*)bufsel(o_sel);

    int beg = g_rowptr[n];
    int end = g_rowptr[n + 1];
    float g = gamma_l[x_ori[n]];
    float gam = 1.f / (1.f + __expf(-g));

    float4 acc = make_float4(0.f, 0.f, 0.f, 0.f);
    for (int j0 = beg; j0 < end; j0 += 32) {
        int e = j0 + lane;
        int   s = 0;
        float w = 0.f;
        if (e < end) {
            s = g_esrc[e];
            w = __expf(-gam * g_ea2[e]);
        }
        int ne = min(32, end - j0);
        int jj = 0;
        for (; jj + 8 <= ne; jj += 8) {
            float wj[8]; int sj[8]; uint2 raw[8];
            #pragma unroll
            for (int q = 0; q < 8; q++) {
                wj[q] = __shfl_sync(0xffffffffu, w, jj + q);
                sj[q] = __shfl_sync(0xffffffffu, s, jj + q);
            }
            #pragma unroll
            for (int q = 0; q < 8; q++)
                raw[q] = *((const uint2*)(g_h16 + (size_t)sj[q] * HID) + lane);
            #pragma unroll
            for (int q = 0; q < 8; q++) {
                float2 fa = __half22float2(*(__half2*)&raw[q].x);
                float2 fb = __half22float2(*(__half2*)&raw[q].y);
                acc.x = fmaf(wj[q], fa.x, acc.x);
                acc.y = fmaf(wj[q], fa.y, acc.y);
                acc.z = fmaf(wj[q], fb.x, acc.z);
                acc.w = fmaf(wj[q], fb.y, acc.w);
            }
        }
        for (; jj < ne; jj++) {
            float wj = __shfl_sync(0xffffffffu, w, jj);
            int   sj = __shfl_sync(0xffffffffu, s, jj);
            uint2 raw = *((const uint2*)(g_h16 + (size_t)sj * HID) + lane);
            float2 fa = __half22float2(*(__half2*)&raw.x);
            float2 fb = __half22float2(*(__half2*)&raw.y);
            acc.x = fmaf(wj, fa.x, acc.x);
            acc.y = fmaf(wj, fa.y, acc.y);
            acc.z = fmaf(wj, fb.x, acc.z);
            acc.w = fmaf(wj, fb.y, acc.w);
        }
    }

    float4 xv = X4[(size_t)n * 32 + lane];
    float4 y;
    y.x = acc.x + xv.x; y.y = acc.y + xv.y;
    y.z = acc.z + xv.z; y.w = acc.w + xv.w;
    float ss = y.x * y.x + y.y * y.y + y.z * y.z + y.w * y.w;
    #pragma unroll
    for (int o = 16; o > 0; o >>= 1) ss += __shfl_xor_sync(0xffffffffu, ss, o);
    float inv = 1.f / fmaxf(sqrtf(ss), 1e-12f);
    y.x *= inv; y.y *= inv; y.z *= inv; y.w *= inv;
    O4[(size_t)n * 32 + lane] = y;
}

// ---------------- graph pooling + head ---------------------------------------
__global__ void dot_scatter_kernel(int x_sel, const float* __restrict__ wp,
                                   const int* __restrict__ batch_ids,
                                   float* __restrict__ out) {
    const float* X = bufsel(x_sel);
    int warp = (blockIdx.x * blockDim.x + threadIdx.x) >> 5;
    if (warp >= NN) return;
    int lane = threadIdx.x & 31;
    float4 x4 = ((const float4*)(X + (size_t)warp * HID))[lane];
    float4 w4 = ((const float4*)wp)[lane];
    float p = x4.x * w4.x + x4.y * w4.y + x4.z * w4.z + x4.w * w4.w;
    #pragma unroll
    for (int o = 16; o > 0; o >>= 1) p += __shfl_xor_sync(0xffffffffu, p, o);
    if (lane == 0) atomicAdd(&out[batch_ids[warp]], p);
}

// ---------------- launch ------------------------------------------------------
extern "C" void kernel_launch(void* const* d_in, const int* in_sizes, int n_in,
                              void* d_out, int out_size) {
    const int*   x_ori     = (const int*)d_in[0];
    const int*   edge_idx  = (const int*)d_in[1];   // [2, NE]
    const float* edge_attr = (const float*)d_in[2]; // [NE, 1]
    const int*   batch_ids = (const int*)d_in[3];
    const float* embd_w    = (const float*)d_in[4];  // [100,128]
    const float* gamma_w   = (const float*)d_in[5];  // [3,100,1]
    const float* w_atom_W  = (const float*)d_in[6];  // [3,128,128]
    const float* w_atom_b  = (const float*)d_in[7];  // [3,128]
    const float* lin_W     = (const float*)d_in[8];  // [2,128,128]
    const float* lin_b     = (const float*)d_in[9];  // [2,128]
    const float* wp_W      = (const float*)d_in[10]; // [128,1]
    const float* wp_b      = (const float*)d_in[11]; // [1]
    float* out = (float*)d_out;

    const int* e_src = edge_idx;
    const int* e_dst = edge_idx + NE;

    const int GEMM_SMEM = (HID * WPAD + 128 * HID) * (int)sizeof(float);
    static bool attr_set = false;
    if (!attr_set) {
        cudaFuncSetAttribute(gemm_relu_kernel,
                             cudaFuncAttributeMaxDynamicSharedMemorySize,
                             GEMM_SMEM);
        attr_set = true;
    }

    // --- weight pre-transpose + embedding/init ---
    dim3 tgrid(4, 4, 5), tblk(32, 8);
    transpose_w_kernel<<<tgrid, tblk>>>(w_atom_W, lin_W);
    embed_kernel<<<(NN * (HID / 4) + 255) / 256, 256>>>(x_ori, embd_w, wp_b, out);

    // --- edge preprocessing: CSR sorted by dst ---
    count_deg_kernel<<<(NE + 255) / 256, 256>>>(e_dst);
    scan_fused_kernel<<<(NN + 1023) / 1024, 1024>>>();
    scatter_edges_kernel<<<(NE + 255) / 256, 256>>>(e_src, e_dst, edge_attr);

    // --- GNN layers: x ping-pong buf0 <-> buf2, h in fp16 g_h16 ---
    const int GBLKS = (NN + 127) / 128;
    int cur = 0;
    for (int l = 0; l < NLAYERS; l++) {
        int nxt = (cur == 0) ? 2 : 0;
        gemm_relu_kernel<<<GBLKS, 512, GEMM_SMEM>>>(
            cur, 3, l, w_atom_b + (size_t)l * HID);
        agg_norm_kernel<<<(NN * 32 + 255) / 256, 256>>>(
            cur, nxt, gamma_w + (size_t)l * NATOMS, x_ori);
        cur = nxt;
    }

    // --- output MLP (fp32 path) ---
    int o1 = (cur == 0) ? 2 : 0;
    gemm_relu_kernel<<<GBLKS, 512, GEMM_SMEM>>>(cur, 1, 3, lin_b);
    gemm_relu_kernel<<<GBLKS, 512, GEMM_SMEM>>>(1, o1, 4, lin_b + HID);

    // --- pooling + head ---
    dot_scatter_kernel<<<(NN * 32 + 255) / 256, 256>>>(o1, wp_W, batch_ids, out);
}

// round 11
// speedup vs baseline: 1.1479x; 1.1479x over previous
#include <cuda_runtime.h>
#include <cuda_fp16.h>
#include <math.h>

#define NN      50000
#define NE      800000
#define HID     128
#define NG      1024
#define NATOMS  100
#define NLAYERS 3
#define WPAD    132          // stride 132 words: conflict-free LDS128 on Wt

// ---------------- scratch (device globals; no allocation allowed) -------------
__device__ float  g_buf0[NN * HID];   // sel 0
__device__ float  g_buf1[NN * HID];   // sel 1
__device__ float  g_buf2[NN * HID];   // sel 2
__device__ __half g_h16[NN * HID];    // fp16 h for edge gathers
__device__ float  g_wt[5 * HID * HID];// pre-transposed weights Wt[c][k]
__device__ int   g_deg[NN + 1];
__device__ int   g_rowptr[NN + 1];
__device__ int   g_cursor[NN];
__device__ int   g_bsum[64];
__device__ int   g_esrc[NE];
__device__ float g_ea2[NE];

__device__ __forceinline__ float* bufsel(int s) {
    return s == 0 ? g_buf0 : (s == 1 ? g_buf1 : g_buf2);
}

// packed f32x2 FMA: d = a*b + d elementwise on two fp32 lanes
__device__ __forceinline__ void ffma2(unsigned long long& d,
                                      unsigned long long a,
                                      unsigned long long b) {
    asm("fma.rn.f32x2 %0, %1, %2, %0;" : "+l"(d) : "l"(a), "l"(b));
}
__device__ __forceinline__ float2 unpack2(unsigned long long u) {
    float2 v;
    asm("mov.b64 {%0, %1}, %2;" : "=f"(v.x), "=f"(v.y) : "l"(u));
    return v;
}

// ---------------- weight pre-transpose (runs once per launch, ~2us) -----------
// W[k][c] (row-major 128x128) -> g_wt[m][c][k]
__global__ void transpose_w_kernel(const float* __restrict__ wa,
                                   const float* __restrict__ lin) {
    __shared__ float t[32][33];
    int m = blockIdx.z;
    const float* src = (m < 3) ? wa + (size_t)m * HID * HID
                               : lin + (size_t)(m - 3) * HID * HID;
    float* dst = g_wt + (size_t)m * HID * HID;
    int x = blockIdx.x * 32 + threadIdx.x;
    int y0 = blockIdx.y * 32;
    #pragma unroll
    for (int dy = threadIdx.y; dy < 32; dy += 8)
        t[dy][threadIdx.x] = src[(size_t)(y0 + dy) * HID + x];
    __syncthreads();
    int xo = blockIdx.y * 32 + threadIdx.x;
    int yo0 = blockIdx.x * 32;
    #pragma unroll
    for (int dy = threadIdx.y; dy < 32; dy += 8)
        dst[(size_t)(yo0 + dy) * HID + xo] = t[threadIdx.x][dy];
}

// ---------------- embedding gather + all zero-init ----------------------------
__global__ void embed_kernel(const int* __restrict__ x_ori,
                             const float* __restrict__ embd,
                             const float* __restrict__ wp_b,
                             float* __restrict__ out) {
    int i = blockIdx.x * blockDim.x + threadIdx.x;   // over NN*32 float4
    if (i <= NN) g_deg[i] = 0;
    if (i < NN)  g_cursor[i] = 0;
    if (i < NG)  out[i] = wp_b[0];
    if (i >= NN * (HID / 4)) return;
    int n = i >> 5;
    int c = i & 31;
    ((float4*)g_buf0)[i] = ((const float4*)(embd + x_ori[n] * HID))[c];
}

// ---------------- edge preprocessing ----------------------------------------
__global__ void count_deg_kernel(const int* __restrict__ dst) {
    int e = blockIdx.x * blockDim.x + threadIdx.x;
    if (e < NE) atomicAdd(&g_deg[dst[e]], 1);
}

// per-1024-chunk local exclusive scan + block sums (grid = 49)
__global__ void scan_local_kernel() {
    __shared__ int wsum[32];
    int tid = threadIdx.x;
    int i = blockIdx.x * 1024 + tid;
    int v = (i < NN) ? g_deg[i] : 0;
    int x = v;
    #pragma unroll
    for (int o = 1; o < 32; o <<= 1) {
        int y = __shfl_up_sync(0xffffffffu, x, o);
        if ((tid & 31) >= o) x += y;
    }
    if ((tid & 31) == 31) wsum[tid >> 5] = x;
    __syncthreads();
    if (tid < 32) {
        int w = wsum[tid];
        #pragma unroll
        for (int o = 1; o < 32; o <<= 1) {
            int y = __shfl_up_sync(0xffffffffu, w, o);
            if (tid >= o) w += y;
        }
        wsum[tid] = w;
    }
    __syncthreads();
    int incl = x + ((tid >= 32) ? wsum[(tid >> 5) - 1] : 0);
    if (i < NN) g_rowptr[i] = incl - v;          // local exclusive
    if (tid == 1023) g_bsum[blockIdx.x] = incl;  // chunk total
}

// scan the 49 chunk sums (1 block, 64 threads)
__global__ void scan_bsums_kernel() {
    __shared__ int w0tot;
    int tid = threadIdx.x;
    int v = (tid < 49) ? g_bsum[tid] : 0;
    int x = v;
    #pragma unroll
    for (int o = 1; o < 32; o <<= 1) {
        int y = __shfl_up_sync(0xffffffffu, x, o);
        if ((tid & 31) >= o) x += y;
    }
    if (tid == 31) w0tot = x;
    __syncthreads();
    if (tid >= 32) x += w0tot;
    if (tid < 49) g_bsum[tid] = x - v;           // exclusive
}

__global__ void scan_add_kernel() {
    int tid = threadIdx.x;
    int i = blockIdx.x * 1024 + tid;
    if (i < NN) g_rowptr[i] += g_bsum[blockIdx.x];
    if (i == NN - 1) g_rowptr[NN] = NE;
}

__global__ void scatter_edges_kernel(const int* __restrict__ src,
                                     const int* __restrict__ dst,
                                     const float* __restrict__ ea) {
    int e = blockIdx.x * blockDim.x + threadIdx.x;
    if (e >= NE) return;
    int d = dst[e];
    int p = g_rowptr[d] + atomicAdd(&g_cursor[d], 1);
    g_esrc[p] = src[e];
    float a = ea[e];
    g_ea2[p] = a * a;
}

// ---------------- GEMM + ReLU via packed f32x2 --------------------------------
// block = 512 threads, tile = 128 rows x 128 cols, K=128 in smem, 1 CTA/SM.
// Wt (pre-transposed in global) staged coalesced + conflict-free.
// Warp handles 8 rows: A-operand smem loads are warp-broadcast (N=1 phases).
// out_sel 0/1/2 -> fp32 buffers; 3 -> fp16 g_h16; 4 -> fused pooling head.
__global__ void __launch_bounds__(512, 1)
gemm_relu_kernel(int in_sel, int out_sel, int wsel,
                 const float* __restrict__ b,
                 const float* __restrict__ wp,
                 const int* __restrict__ batch_ids,
                 float* __restrict__ out) {
    extern __shared__ float sm[];
    float* Wt = sm;                  // [128 c][WPAD k]
    float* As = sm + HID * WPAD;     // [128 r][128 k]
    const float* X = bufsel(in_sel);
    const float* WtG = g_wt + (size_t)wsel * HID * HID;
    int tid  = threadIdx.x;
    int lane = tid & 31;
    int wid  = tid >> 5;             // 0..15
    int row0 = blockIdx.x * 128;

    // stage Wt: consecutive lanes -> consecutive k words (conflict-free, coalesced)
    #pragma unroll
    for (int i = tid; i < HID * HID; i += 512) {
        int c = i >> 7, k = i & 127;
        Wt[c * WPAD + k] = WtG[i];
    }
    // stage A rows (float4, conflict-free)
    #pragma unroll
    for (int i = tid; i < 128 * (HID / 4); i += 512) {
        int r = i >> 5, c = i & 31;
        int row = row0 + r;
        ((float4*)As)[i] = (row < NN) ? ((const float4*)(X + (size_t)row * HID))[c]
                                      : make_float4(0.f, 0.f, 0.f, 0.f);
    }
    __syncthreads();

    unsigned long long acc[8][4];    // [row][colgrp], f32x2 = even/odd-k partials
    #pragma unroll
    for (int r = 0; r < 8; r++)
        #pragma unroll
        for (int j = 0; j < 4; j++) acc[r][j] = 0ull;

    const int rbase = wid * 8;
    #pragma unroll 4
    for (int k4 = 0; k4 < 32; k4++) {
        ulonglong2 wv[4];
        #pragma unroll
        for (int j = 0; j < 4; j++)
            wv[j] = *(const ulonglong2*)&Wt[(lane + 32 * j) * WPAD + 4 * k4];
        #pragma unroll
        for (int r = 0; r < 8; r++) {
            ulonglong2 av = ((const ulonglong2*)As)[(rbase + r) * 32 + k4];
            #pragma unroll
            for (int j = 0; j < 4; j++) {
                ffma2(acc[r][j], av.x, wv[j].x);
                ffma2(acc[r][j], av.y, wv[j].y);
            }
        }
    }

    float bb[4];
    #pragma unroll
    for (int j = 0; j < 4; j++) bb[j] = b[lane + 32 * j];

    if (out_sel == 3) {
        #pragma unroll
        for (int r = 0; r < 8; r++) {
            int row = row0 + rbase + r;
            if (row < NN) {
                #pragma unroll
                for (int j = 0; j < 4; j++) {
                    float2 p = unpack2(acc[r][j]);
                    float v = fmaxf(p.x + p.y + bb[j], 0.f);
                    g_h16[(size_t)row * HID + lane + 32 * j] = __float2half(v);
                }
            }
        }
    } else if (out_sel == 4) {
        // fused head: p[row] = sum_c relu(gemm[row,c]) * wp[c]; atomic into graph
        float wpv[4];
        #pragma unroll
        for (int j = 0; j < 4; j++) wpv[j] = wp[lane + 32 * j];
        #pragma unroll
        for (int r = 0; r < 8; r++) {
            int row = row0 + rbase + r;
            float p = 0.f;
            #pragma unroll
            for (int j = 0; j < 4; j++) {
                float2 u = unpack2(acc[r][j]);
                p = fmaf(fmaxf(u.x + u.y + bb[j], 0.f), wpv[j], p);
            }
            #pragma unroll
            for (int o = 16; o > 0; o >>= 1)
                p += __shfl_xor_sync(0xffffffffu, p, o);
            if (lane == 0 && row < NN)
                atomicAdd(&out[batch_ids[row]], p);
        }
    } else {
        float* O = bufsel(out_sel);
        #pragma unroll
        for (int r = 0; r < 8; r++) {
            int row = row0 + rbase + r;
            if (row < NN) {
                #pragma unroll
                for (int j = 0; j < 4; j++) {
                    float2 p = unpack2(acc[r][j]);
                    O[(size_t)row * HID + lane + 32 * j] =
                        fmaxf(p.x + p.y + bb[j], 0.f);
                }
            }
        }
    }
}

// ---------------- aggregation + residual + normalize -------------------------
// one WARP per node; lane holds 4 adjacent cols (fp16 gather = 8B/lane);
// inner loop batched by 8 for MLP=8
__global__ void agg_norm_kernel(int x_sel, int o_sel,
                                const float* __restrict__ gamma_l,
                                const int* __restrict__ x_ori) {
    int n = (blockIdx.x * blockDim.x + threadIdx.x) >> 5;
    int lane = threadIdx.x & 31;
    const float4* X4 = (const float4*)bufsel(x_sel);
    float4*       O4 = (float4*)bufsel(o_sel);

    int beg = g_rowptr[n];
    int end = g_rowptr[n + 1];
    float g = gamma_l[x_ori[n]];
    float gam = 1.f / (1.f + __expf(-g));

    float4 acc = make_float4(0.f, 0.f, 0.f, 0.f);
    for (int j0 = beg; j0 < end; j0 += 32) {
        int e = j0 + lane;
        int   s = 0;
        float w = 0.f;
        if (e < end) {
            s = g_esrc[e];
            w = __expf(-gam * g_ea2[e]);
        }
        int ne = min(32, end - j0);
        int jj = 0;
        for (; jj + 8 <= ne; jj += 8) {
            float wj[8]; int sj[8]; uint2 raw[8];
            #pragma unroll
            for (int q = 0; q < 8; q++) {
                wj[q] = __shfl_sync(0xffffffffu, w, jj + q);
                sj[q] = __shfl_sync(0xffffffffu, s, jj + q);
            }
            #pragma unroll
            for (int q = 0; q < 8; q++)
                raw[q] = *((const uint2*)(g_h16 + (size_t)sj[q] * HID) + lane);
            #pragma unroll
            for (int q = 0; q < 8; q++) {
                float2 fa = __half22float2(*(__half2*)&raw[q].x);
                float2 fb = __half22float2(*(__half2*)&raw[q].y);
                acc.x = fmaf(wj[q], fa.x, acc.x);
                acc.y = fmaf(wj[q], fa.y, acc.y);
                acc.z = fmaf(wj[q], fb.x, acc.z);
                acc.w = fmaf(wj[q], fb.y, acc.w);
            }
        }
        for (; jj < ne; jj++) {
            float wj = __shfl_sync(0xffffffffu, w, jj);
            int   sj = __shfl_sync(0xffffffffu, s, jj);
            uint2 raw = *((const uint2*)(g_h16 + (size_t)sj * HID) + lane);
            float2 fa = __half22float2(*(__half2*)&raw.x);
            float2 fb = __half22float2(*(__half2*)&raw.y);
            acc.x = fmaf(wj, fa.x, acc.x);
            acc.y = fmaf(wj, fa.y, acc.y);
            acc.z = fmaf(wj, fb.x, acc.z);
            acc.w = fmaf(wj, fb.y, acc.w);
        }
    }

    float4 xv = X4[(size_t)n * 32 + lane];
    float4 y;
    y.x = acc.x + xv.x; y.y = acc.y + xv.y;
    y.z = acc.z + xv.z; y.w = acc.w + xv.w;
    float ss = y.x * y.x + y.y * y.y + y.z * y.z + y.w * y.w;
    #pragma unroll
    for (int o = 16; o > 0; o >>= 1) ss += __shfl_xor_sync(0xffffffffu, ss, o);
    float inv = 1.f / fmaxf(sqrtf(ss), 1e-12f);
    y.x *= inv; y.y *= inv; y.z *= inv; y.w *= inv;
    O4[(size_t)n * 32 + lane] = y;
}

// ---------------- launch ------------------------------------------------------
extern "C" void kernel_launch(void* const* d_in, const int* in_sizes, int n_in,
                              void* d_out, int out_size) {
    const int*   x_ori     = (const int*)d_in[0];
    const int*   edge_idx  = (const int*)d_in[1];   // [2, NE]
    const float* edge_attr = (const float*)d_in[2]; // [NE, 1]
    const int*   batch_ids = (const int*)d_in[3];
    const float* embd_w    = (const float*)d_in[4];  // [100,128]
    const float* gamma_w   = (const float*)d_in[5];  // [3,100,1]
    const float* w_atom_W  = (const float*)d_in[6];  // [3,128,128]
    const float* w_atom_b  = (const float*)d_in[7];  // [3,128]
    const float* lin_W     = (const float*)d_in[8];  // [2,128,128]
    const float* lin_b     = (const float*)d_in[9];  // [2,128]
    const float* wp_W      = (const float*)d_in[10]; // [128,1]
    const float* wp_b      = (const float*)d_in[11]; // [1]
    float* out = (float*)d_out;

    const int* e_src = edge_idx;
    const int* e_dst = edge_idx + NE;

    const int GEMM_SMEM = (HID * WPAD + 128 * HID) * (int)sizeof(float);
    static bool attr_set = false;
    if (!attr_set) {
        cudaFuncSetAttribute(gemm_relu_kernel,
                             cudaFuncAttributeMaxDynamicSharedMemorySize,
                             GEMM_SMEM);
        attr_set = true;
    }

    const int NCHUNK = (NN + 1023) / 1024;   // 49

    // --- weight pre-transpose + embedding/init ---
    dim3 tgrid(4, 4, 5), tblk(32, 8);
    transpose_w_kernel<<<tgrid, tblk>>>(w_atom_W, lin_W);
    embed_kernel<<<(NN * (HID / 4) + 255) / 256, 256>>>(x_ori, embd_w, wp_b, out);

    // --- edge preprocessing: CSR sorted by dst ---
    count_deg_kernel<<<(NE + 255) / 256, 256>>>(e_dst);
    scan_local_kernel<<<NCHUNK, 1024>>>();
    scan_bsums_kernel<<<1, 64>>>();
    scan_add_kernel<<<NCHUNK, 1024>>>();
    scatter_edges_kernel<<<(NE + 255) / 256, 256>>>(e_src, e_dst, edge_attr);

    // --- GNN layers: x ping-pong buf0 <-> buf2, h in fp16 g_h16 ---
    const int GBLKS = (NN + 127) / 128;
    int cur = 0;
    for (int l = 0; l < NLAYERS; l++) {
        int nxt = (cur == 0) ? 2 : 0;
        gemm_relu_kernel<<<GBLKS, 512, GEMM_SMEM>>>(
            cur, 3, l, w_atom_b + (size_t)l * HID, wp_W, batch_ids, out);
        agg_norm_kernel<<<(NN * 32 + 255) / 256, 256>>>(
            cur, nxt, gamma_w + (size_t)l * NATOMS, x_ori);
        cur = nxt;
    }

    // --- output MLP: first layer to buf1, second fused with pooling head ---
    gemm_relu_kernel<<<GBLKS, 512, GEMM_SMEM>>>(cur, 1, 3, lin_b, wp_W, batch_ids, out);
    gemm_relu_kernel<<<GBLKS, 512, GEMM_SMEM>>>(1, 4, 4, lin_b + HID, wp_W, batch_ids, out);
}

// round 14
// speedup vs baseline: 1.8097x; 1.5766x over previous
#include <cuda_runtime.h>
#include <cuda_fp16.h>
#include <mma.h>
#include <math.h>

using namespace nvcuda;

#define NN      50000
#define NE      800000
#define HID     128
#define NG      1024
#define NATOMS  100
#define NLAYERS 3
#define HSTR    136          // half stride: 272B rows, 16B-aligned, ldmatrix-friendly
#define CSTR    132          // float stride for C epilogue

// ---------------- scratch (device globals; no allocation allowed) -------------
__device__ float  g_buf0[NN * HID];   // sel 0
__device__ float  g_buf1[NN * HID];   // sel 1
__device__ float  g_buf2[NN * HID];   // sel 2
__device__ __half g_h16[NN * HID];    // fp16 h for edge gathers
__device__ __half g_w16[5 * HID * HID]; // fp16 weights (row-major, as-is)
__device__ int   g_deg[NN + 1];
__device__ int   g_rowptr[NN + 1];
__device__ int   g_cursor[NN];
__device__ int   g_bsum[64];
__device__ int   g_esrc[NE];
__device__ float g_ea2[NE];

__device__ __forceinline__ float* bufsel(int s) {
    return s == 0 ? g_buf0 : (s == 1 ? g_buf1 : g_buf2);
}

// ---------------- weight fp32 -> fp16 (once per launch, trivial) ---------------
__global__ void convert_w_kernel(const float* __restrict__ wa,
                                 const float* __restrict__ lin) {
    int i = blockIdx.x * blockDim.x + threadIdx.x;
    if (i >= 5 * HID * HID) return;
    float v = (i < 3 * HID * HID) ? wa[i] : lin[i - 3 * HID * HID];
    g_w16[i] = __float2half(v);
}

// ---------------- embedding gather + all zero-init ----------------------------
__global__ void embed_kernel(const int* __restrict__ x_ori,
                             const float* __restrict__ embd,
                             const float* __restrict__ wp_b,
                             float* __restrict__ out) {
    int i = blockIdx.x * blockDim.x + threadIdx.x;   // over NN*32 float4
    if (i <= NN) g_deg[i] = 0;
    if (i < NN)  g_cursor[i] = 0;
    if (i < NG)  out[i] = wp_b[0];
    if (i >= NN * (HID / 4)) return;
    int n = i >> 5;
    int c = i & 31;
    ((float4*)g_buf0)[i] = ((const float4*)(embd + x_ori[n] * HID))[c];
}

// ---------------- edge preprocessing ----------------------------------------
__global__ void count_deg_kernel(const int* __restrict__ dst) {
    int e = blockIdx.x * blockDim.x + threadIdx.x;
    if (e < NE) atomicAdd(&g_deg[dst[e]], 1);
}

// per-1024-chunk local exclusive scan + block sums (grid = 49)
__global__ void scan_local_kernel() {
    __shared__ int wsum[32];
    int tid = threadIdx.x;
    int i = blockIdx.x * 1024 + tid;
    int v = (i < NN) ? g_deg[i] : 0;
    int x = v;
    #pragma unroll
    for (int o = 1; o < 32; o <<= 1) {
        int y = __shfl_up_sync(0xffffffffu, x, o);
        if ((tid & 31) >= o) x += y;
    }
    if ((tid & 31) == 31) wsum[tid >> 5] = x;
    __syncthreads();
    if (tid < 32) {
        int w = wsum[tid];
        #pragma unroll
        for (int o = 1; o < 32; o <<= 1) {
            int y = __shfl_up_sync(0xffffffffu, w, o);
            if (tid >= o) w += y;
        }
        wsum[tid] = w;
    }
    __syncthreads();
    int incl = x + ((tid >= 32) ? wsum[(tid >> 5) - 1] : 0);
    if (i < NN) g_rowptr[i] = incl - v;          // local exclusive
    if (tid == 1023) g_bsum[blockIdx.x] = incl;  // chunk total
}

// scan the 49 chunk sums (1 block, 64 threads)
__global__ void scan_bsums_kernel() {
    __shared__ int w0tot;
    int tid = threadIdx.x;
    int v = (tid < 49) ? g_bsum[tid] : 0;
    int x = v;
    #pragma unroll
    for (int o = 1; o < 32; o <<= 1) {
        int y = __shfl_up_sync(0xffffffffu, x, o);
        if ((tid & 31) >= o) x += y;
    }
    if (tid == 31) w0tot = x;
    __syncthreads();
    if (tid >= 32) x += w0tot;
    if (tid < 49) g_bsum[tid] = x - v;           // exclusive
}

__global__ void scan_add_kernel() {
    int tid = threadIdx.x;
    int i = blockIdx.x * 1024 + tid;
    if (i < NN) g_rowptr[i] += g_bsum[blockIdx.x];
    if (i == NN - 1) g_rowptr[NN] = NE;
}

__global__ void scatter_edges_kernel(const int* __restrict__ src,
                                     const int* __restrict__ dst,
                                     const float* __restrict__ ea) {
    int e = blockIdx.x * blockDim.x + threadIdx.x;
    if (e >= NE) return;
    int d = dst[e];
    int p = g_rowptr[d] + atomicAdd(&g_cursor[d], 1);
    g_esrc[p] = src[e];
    float a = ea[e];
    g_ea2[p] = a * a;
}

// ---------------- GEMM + ReLU via wmma (HMMA, fp16 in / fp32 accum) -----------
// block = 512 threads (16 warps), tile = 128 rows x 128 cols, K=128 in smem.
// Warp grid 4x4; each warp owns a 32x32 patch (2x2 wmma 16x16x16 tiles).
// out_sel 0/1/2 -> fp32 buffers; 3 -> fp16 g_h16; 4 -> fused pooling head.
__global__ void __launch_bounds__(512, 2)
gemm_relu_kernel(int in_sel, int out_sel, int wsel,
                 const float* __restrict__ b,
                 const float* __restrict__ wp,
                 const int* __restrict__ batch_ids,
                 float* __restrict__ out) {
    extern __shared__ char smraw[];
    __half* Ah = (__half*)smraw;            // [128][HSTR]
    __half* Bh = Ah + 128 * HSTR;           // [128][HSTR]
    float*  Cs = (float*)smraw;             // [128][CSTR]  (reused after sync)
    const float* X = bufsel(in_sel);
    const __half* WhG = g_w16 + (size_t)wsel * HID * HID;
    int tid  = threadIdx.x;
    int wid  = tid >> 5;             // 0..15
    int row0 = blockIdx.x * 128;

    // stage A: fp32 -> fp16 convert (row stride HSTR)
    #pragma unroll
    for (int i = tid; i < 128 * (HID / 4); i += 512) {
        int r = i >> 5, c4 = i & 31;
        int row = row0 + r;
        float4 v = (row < NN) ? ((const float4*)(X + (size_t)row * HID))[c4]
                              : make_float4(0.f, 0.f, 0.f, 0.f);
        __half2* dst = (__half2*)&Ah[r * HSTR + c4 * 4];
        dst[0] = __floats2half2_rn(v.x, v.y);
        dst[1] = __floats2half2_rn(v.z, v.w);
    }
    // stage B: fp16 weights, straight copy (uint4 = 16B = 8 halves per chunk)
    #pragma unroll
    for (int i = tid; i < 128 * (HID / 8); i += 512) {
        int r = i >> 4, c8 = i & 15;
        *(uint4*)&Bh[r * HSTR + c8 * 8] = ((const uint4*)(WhG + (size_t)r * HID))[c8];
    }
    __syncthreads();

    // warp tile: (wm, wn) in 4x4; covers rows [wm*32, +32), cols [wn*32, +32)
    int wm = wid >> 2, wn = wid & 3;
    wmma::fragment<wmma::accumulator, 16, 16, 16, float> c[2][2];
    #pragma unroll
    for (int i = 0; i < 2; i++)
        #pragma unroll
        for (int j = 0; j < 2; j++) wmma::fill_fragment(c[i][j], 0.f);

    #pragma unroll
    for (int k = 0; k < 8; k++) {
        wmma::fragment<wmma::matrix_a, 16, 16, 16, __half, wmma::row_major> a[2];
        wmma::fragment<wmma::matrix_b, 16, 16, 16, __half, wmma::row_major> bf[2];
        #pragma unroll
        for (int i = 0; i < 2; i++)
            wmma::load_matrix_sync(a[i], Ah + (wm * 32 + i * 16) * HSTR + k * 16, HSTR);
        #pragma unroll
        for (int j = 0; j < 2; j++)
            wmma::load_matrix_sync(bf[j], Bh + (k * 16) * HSTR + wn * 32 + j * 16, HSTR);
        #pragma unroll
        for (int i = 0; i < 2; i++)
            #pragma unroll
            for (int j = 0; j < 2; j++)
                wmma::mma_sync(c[i][j], a[i], bf[j], c[i][j]);
    }

    __syncthreads();   // done reading Ah/Bh; reuse smem as C
    #pragma unroll
    for (int i = 0; i < 2; i++)
        #pragma unroll
        for (int j = 0; j < 2; j++)
            wmma::store_matrix_sync(Cs + (wm * 32 + i * 16) * CSTR + wn * 32 + j * 16,
                                    c[i][j], CSTR, wmma::mem_row_major);
    __syncthreads();

    if (out_sel == 4) {
        // fused head: p[row] = sum_c relu(C[row,c]+b[c]) * wp[c]; atomic per graph
        int r = tid >> 2, q = tid & 3;
        int row = row0 + r;
        float p = 0.f;
        #pragma unroll 8
        for (int c0 = q * 32; c0 < q * 32 + 32; c0++) {
            float v = Cs[r * CSTR + c0] + b[c0];
            p = fmaf(fmaxf(v, 0.f), wp[c0], p);
        }
        p += __shfl_xor_sync(0xffffffffu, p, 1);
        p += __shfl_xor_sync(0xffffffffu, p, 2);
        if (q == 0 && row < NN)
            atomicAdd(&out[batch_ids[row]], p);
    } else if (out_sel == 3) {
        #pragma unroll
        for (int i = tid; i < 128 * 32; i += 512) {
            int r = i >> 5, c4 = i & 31;
            int row = row0 + r;
            if (row < NN) {
                #pragma unroll
                for (int u = 0; u < 4; u++) {
                    int cc = c4 * 4 + u;
                    float v = fmaxf(Cs[r * CSTR + cc] + b[cc], 0.f);
                    g_h16[(size_t)row * HID + cc] = __float2half(v);
                }
            }
        }
    } else {
        float* O = bufsel(out_sel);
        #pragma unroll
        for (int i = tid; i < 128 * 32; i += 512) {
            int r = i >> 5, c4 = i & 31;
            int row = row0 + r;
            if (row < NN) {
                float4 o;
                o.x = fmaxf(Cs[r * CSTR + c4 * 4 + 0] + b[c4 * 4 + 0], 0.f);
                o.y = fmaxf(Cs[r * CSTR + c4 * 4 + 1] + b[c4 * 4 + 1], 0.f);
                o.z = fmaxf(Cs[r * CSTR + c4 * 4 + 2] + b[c4 * 4 + 2], 0.f);
                o.w = fmaxf(Cs[r * CSTR + c4 * 4 + 3] + b[c4 * 4 + 3], 0.f);
                ((float4*)(O + (size_t)row * HID))[c4] = o;
            }
        }
    }
}

// ---------------- aggregation + residual + normalize -------------------------
// one WARP per node; lane holds 4 adjacent cols (fp16 gather = 8B/lane);
// inner loop batched by 8 for MLP=8
__global__ void agg_norm_kernel(int x_sel, int o_sel,
                                const float* __restrict__ gamma_l,
                                const int* __restrict__ x_ori) {
    int n = (blockIdx.x * blockDim.x + threadIdx.x) >> 5;
    int lane = threadIdx.x & 31;
    const float4* X4 = (const float4*)bufsel(x_sel);
    float4*       O4 = (float4*)bufsel(o_sel);

    int beg = g_rowptr[n];
    int end = g_rowptr[n + 1];
    float g = gamma_l[x_ori[n]];
    float gam = 1.f / (1.f + __expf(-g));

    float4 acc = make_float4(0.f, 0.f, 0.f, 0.f);
    for (int j0 = beg; j0 < end; j0 += 32) {
        int e = j0 + lane;
        int   s = 0;
        float w = 0.f;
        if (e < end) {
            s = g_esrc[e];
            w = __expf(-gam * g_ea2[e]);
        }
        int ne = min(32, end - j0);
        int jj = 0;
        for (; jj + 8 <= ne; jj += 8) {
            float wj[8]; int sj[8]; uint2 raw[8];
            #pragma unroll
            for (int q = 0; q < 8; q++) {
                wj[q] = __shfl_sync(0xffffffffu, w, jj + q);
                sj[q] = __shfl_sync(0xffffffffu, s, jj + q);
            }
            #pragma unroll
            for (int q = 0; q < 8; q++)
                raw[q] = *((const uint2*)(g_h16 + (size_t)sj[q] * HID) + lane);
            #pragma unroll
            for (int q = 0; q < 8; q++) {
                float2 fa = __half22float2(*(__half2*)&raw[q].x);
                float2 fb = __half22float2(*(__half2*)&raw[q].y);
                acc.x = fmaf(wj[q], fa.x, acc.x);
                acc.y = fmaf(wj[q], fa.y, acc.y);
                acc.z = fmaf(wj[q], fb.x, acc.z);
                acc.w = fmaf(wj[q], fb.y, acc.w);
            }
        }
        for (; jj < ne; jj++) {
            float wj = __shfl_sync(0xffffffffu, w, jj);
            int   sj = __shfl_sync(0xffffffffu, s, jj);
            uint2 raw = *((const uint2*)(g_h16 + (size_t)sj * HID) + lane);
            float2 fa = __half22float2(*(__half2*)&raw.x);
            float2 fb = __half22float2(*(__half2*)&raw.y);
            acc.x = fmaf(wj, fa.x, acc.x);
            acc.y = fmaf(wj, fa.y, acc.y);
            acc.z = fmaf(wj, fb.x, acc.z);
            acc.w = fmaf(wj, fb.y, acc.w);
        }
    }

    float4 xv = X4[(size_t)n * 32 + lane];
    float4 y;
    y.x = acc.x + xv.x; y.y = acc.y + xv.y;
    y.z = acc.z + xv.z; y.w = acc.w + xv.w;
    float ss = y.x * y.x + y.y * y.y + y.z * y.z + y.w * y.w;
    #pragma unroll
    for (int o = 16; o > 0; o >>= 1) ss += __shfl_xor_sync(0xffffffffu, ss, o);
    float inv = 1.f / fmaxf(sqrtf(ss), 1e-12f);
    y.x *= inv; y.y *= inv; y.z *= inv; y.w *= inv;
    O4[(size_t)n * 32 + lane] = y;
}

// ---------------- launch ------------------------------------------------------
extern "C" void kernel_launch(void* const* d_in, const int* in_sizes, int n_in,
                              void* d_out, int out_size) {
    const int*   x_ori     = (const int*)d_in[0];
    const int*   edge_idx  = (const int*)d_in[1];   // [2, NE]
    const float* edge_attr = (const float*)d_in[2]; // [NE, 1]
    const int*   batch_ids = (const int*)d_in[3];
    const float* embd_w    = (const float*)d_in[4];  // [100,128]
    const float* gamma_w   = (const float*)d_in[5];  // [3,100,1]
    const float* w_atom_W  = (const float*)d_in[6];  // [3,128,128]
    const float* w_atom_b  = (const float*)d_in[7];  // [3,128]
    const float* lin_W     = (const float*)d_in[8];  // [2,128,128]
    const float* lin_b     = (const float*)d_in[9];  // [2,128]
    const float* wp_W      = (const float*)d_in[10]; // [128,1]
    const float* wp_b      = (const float*)d_in[11]; // [1]
    float* out = (float*)d_out;

    const int* e_src = edge_idx;
    const int* e_dst = edge_idx + NE;

    const int GEMM_SMEM = 2 * 128 * HSTR * (int)sizeof(__half);  // 69632 B
    static bool attr_set = false;
    if (!attr_set) {
        cudaFuncSetAttribute(gemm_relu_kernel,
                             cudaFuncAttributeMaxDynamicSharedMemorySize,
                             GEMM_SMEM);
        attr_set = true;
    }

    const int NCHUNK = (NN + 1023) / 1024;   // 49

    // --- weight convert + embedding/init ---
    convert_w_kernel<<<(5 * HID * HID + 255) / 256, 256>>>(w_atom_W, lin_W);
    embed_kernel<<<(NN * (HID / 4) + 255) / 256, 256>>>(x_ori, embd_w, wp_b, out);

    // --- edge preprocessing: CSR sorted by dst ---
    count_deg_kernel<<<(NE + 255) / 256, 256>>>(e_dst);
    scan_local_kernel<<<NCHUNK, 1024>>>();
    scan_bsums_kernel<<<1, 64>>>();
    scan_add_kernel<<<NCHUNK, 1024>>>();
    scatter_edges_kernel<<<(NE + 255) / 256, 256>>>(e_src, e_dst, edge_attr);

    // --- GNN layers: x ping-pong buf0 <-> buf2, h in fp16 g_h16 ---
    const int GBLKS = (NN + 127) / 128;
    int cur = 0;
    for (int l = 0; l < NLAYERS; l++) {
        int nxt = (cur == 0) ? 2 : 0;
        gemm_relu_kernel<<<GBLKS, 512, GEMM_SMEM>>>(
            cur, 3, l, w_atom_b + (size_t)l * HID, wp_W, batch_ids, out);
        agg_norm_kernel<<<(NN * 32 + 255) / 256, 256>>>(
            cur, nxt, gamma_w + (size_t)l * NATOMS, x_ori);
        cur = nxt;
    }

    // --- output MLP: first layer to buf1, second fused with pooling head ---
    gemm_relu_kernel<<<GBLKS, 512, GEMM_SMEM>>>(cur, 1, 3, lin_b, wp_W, batch_ids, out);
    gemm_relu_kernel<<<GBLKS, 512, GEMM_SMEM>>>(1, 4, 4, lin_b + HID, wp_W, batch_ids, out);
}